// round 12
// baseline (speedup 1.0000x reference)
#include <cuda_runtime.h>
#include <cuda_fp16.h>
#include <cstdint>

#define N_NODES 50000
#define F_INF   512
#define H_DIM   128
#define E_MAX   1600000

// ---------------------------------------------------------------------------
// Device scratch
// ---------------------------------------------------------------------------
__device__ __align__(8) float2 g_deg2[N_NODES];   // {sum_w, count}
__device__ float g_dinv[N_NODES];
__device__ int   g_cnt [N_NODES];
__device__ int   g_off [N_NODES];
__device__ int   g_cur [N_NODES];
__device__ int   g_total;
__device__ __align__(16) uint2  g_edges[E_MAX];                    // (src, w) 12.8 MB
__device__ __align__(16) __half g_h   [(size_t)N_NODES * H_DIM];   // 12.8 MB
__device__ __align__(16) __half g_wc16[H_DIM * F_INF];             // Wc^T fp16 [128,512]
__device__ __align__(16) __half g_wl16[F_INF * H_DIM];             // Wl^T fp16 [512,128]

#define SMEM_SWIZZLE_128B(off) ((off) ^ (((off) >> 3) & 0x70))

__device__ __forceinline__ uint32_t smem_to_u32(const void* p) {
    uint32_t a;
    asm("{ .reg .u64 t; cvta.to.shared.u64 t, %1; cvt.u32.u64 %0, t; }"
        : "=r"(a) : "l"(p));
    return a;
}

__device__ __forceinline__ void ldsm_x4(uint32_t* r, uint32_t addr) {
    asm volatile("ldmatrix.sync.aligned.m8n8.x4.shared.b16 {%0,%1,%2,%3}, [%4];"
                 : "=r"(r[0]), "=r"(r[1]), "=r"(r[2]), "=r"(r[3]) : "r"(addr));
}

__device__ __forceinline__ void mma_f16(float* c, const uint32_t* a,
                                        uint32_t b0, uint32_t b1) {
    asm volatile(
        "mma.sync.aligned.m16n8k16.row.col.f32.f16.f16.f32 "
        "{%0,%1,%2,%3}, {%4,%5,%6,%7}, {%8,%9}, {%0,%1,%2,%3};"
        : "+f"(c[0]), "+f"(c[1]), "+f"(c[2]), "+f"(c[3])
        : "r"(a[0]), "r"(a[1]), "r"(a[2]), "r"(a[3]), "r"(b0), "r"(b1));
}

__device__ __forceinline__ uint32_t pack_f16(float x, float y) {
    __half2 p = __floats2half2_rn(x, y);
    return *reinterpret_cast<uint32_t*>(&p);
}

__device__ __forceinline__ void cp_async16(uint32_t smem_addr, const void* gptr) {
    asm volatile("cp.async.cg.shared.global [%0], [%1], 16;"
                 :: "r"(smem_addr), "l"(gptr));
}

// ---------------------------------------------------------------------------
// Init: deg2 reset + transposed fp16 weight conversion
// ---------------------------------------------------------------------------
__global__ void k_init(const float* __restrict__ Wc, const float* __restrict__ Wl, int n) {
    int i = blockIdx.x * blockDim.x + threadIdx.x;
    if (i < n) g_deg2[i] = make_float2(1.0f, 0.0f);
    if (i == 0) g_total = 0;
    if (i < H_DIM * F_INF) {
        int r = i >> 9, c = i & 511;                 // WcT [128,512]
        g_wc16[i] = __float2half(Wc[(size_t)c * H_DIM + r]);
        int r2 = i >> 7, c2 = i & 127;               // WlT [512,128]
        g_wl16[i] = __float2half(Wl[(size_t)c2 * F_INF + r2]);
    }
}

// Single vector reduction per edge: deg += w, cnt += 1
__global__ void k_deg_accum(const int* __restrict__ dst, const float* __restrict__ w, int E) {
    int e = blockIdx.x * blockDim.x + threadIdx.x;
    if (e < E) {
        float2* p = &g_deg2[dst[e]];
        asm volatile("red.global.add.v2.f32 [%0], {%1,%2};"
                     :: "l"(p), "f"(w[e]), "f"(1.0f) : "memory");
    }
}

// dinv + warp-aggregated bin-range assignment
__global__ void k_dinv_assign(int n) {
    int i = blockIdx.x * blockDim.x + threadIdx.x;
    int lane = threadIdx.x & 31;
    int c = 0;
    if (i < n) {
        float2 dg = g_deg2[i];
        g_dinv[i] = (dg.x > 0.0f) ? rsqrtf(dg.x) : 0.0f;
        c = (int)dg.y;
        g_cnt[i] = c;
    }
    int v = c;
#pragma unroll
    for (int o = 1; o < 32; o <<= 1) {
        int t = __shfl_up_sync(0xFFFFFFFFu, v, o);
        if (lane >= o) v += t;
    }
    int warpTotal = __shfl_sync(0xFFFFFFFFu, v, 31);
    int base = 0;
    if (lane == 31 && warpTotal > 0) base = atomicAdd(&g_total, warpTotal);
    base = __shfl_sync(0xFFFFFFFFu, base, 31);
    if (i < n) {
        int off = base + v - c;
        g_off[i] = off;
        g_cur[i] = off;
    }
}

// Fill dst-binned edge list with RAW (src, w)
__global__ void k_fill(const int* __restrict__ src, const int* __restrict__ dst,
                       const float* __restrict__ w, int E) {
    int e = blockIdx.x * blockDim.x + threadIdx.x;
    if (e >= E) return;
    int s = src[e], d = dst[e];
    int pos = atomicAdd(&g_cur[d], 1);
    g_edges[pos] = make_uint2((uint32_t)s, __float_as_uint(__ldg(&w[e])));
}

// ---------------------------------------------------------------------------
// GEMM1: h = x @ Wc, single-pass fp16 (fp32 accumulate), writes g_h fp16.
// A fp32 prefetched into regs (converted on STS); B double-buffered cp.async.
// ---------------------------------------------------------------------------
__global__ __launch_bounds__(256)
void gemm1_f16(const float* __restrict__ A32, int M, int K) {
    extern __shared__ char smem[];
    constexpr int SM_A0 = 0;
    constexpr int SM_B0 = 16384, SM_B1 = 32768;

    uint32_t sbase = smem_to_u32(smem);
    int tid = threadIdx.x;
    int wid = tid >> 5, lane = tid & 31;
    int wm = wid & 3, wn = wid >> 2;
    int rowBase = blockIdx.y * 128;

    float acc[2][8][4];
#pragma unroll
    for (int i = 0; i < 2; i++)
#pragma unroll
        for (int j = 0; j < 8; j++)
#pragma unroll
            for (int k = 0; k < 4; k++) acc[i][j][k] = 0.0f;

    uint32_t lr = lane & 7, lg = lane >> 3;
    int nchunk = K >> 6;

    float4 aR[4][2];
    auto ldA = [&](int c) {
        int k0 = c << 6;
#pragma unroll
        for (int l = 0; l < 4; l++) {
            int t = tid + l * 256;
            int r = t >> 3, q = t & 7;
            int grow = rowBase + r;
            float4 v0 = make_float4(0.f, 0.f, 0.f, 0.f), v1 = v0;
            if (grow < M) {
                const float* ap = A32 + (size_t)grow * K + k0 + q * 8;
                v0 = *(const float4*)ap;
                v1 = *(const float4*)(ap + 4);
            }
            aR[l][0] = v0; aR[l][1] = v1;
        }
    };
    auto stsA = [&]() {
#pragma unroll
        for (int l = 0; l < 4; l++) {
            int t = tid + l * 256;
            int r = t >> 3, q = t & 7;
            float4 v0 = aR[l][0], v1 = aR[l][1];
            uint4 hv;
            hv.x = pack_f16(v0.x, v0.y); hv.y = pack_f16(v0.z, v0.w);
            hv.z = pack_f16(v1.x, v1.y); hv.w = pack_f16(v1.z, v1.w);
            uint32_t sw = SMEM_SWIZZLE_128B((uint32_t)(r * 128 + q * 16));
            *(uint4*)(smem + SM_A0 + sw) = hv;
        }
    };
    auto cpB = [&](int c, int buf) {
        int k0 = c << 6;
        int bb = buf ? SM_B1 : SM_B0;
#pragma unroll
        for (int l = 0; l < 4; l++) {
            int t = tid + l * 256;
            int r = t >> 3, q = t & 7;
            uint32_t sw = SMEM_SWIZZLE_128B((uint32_t)(r * 128 + q * 16));
            cp_async16(sbase + bb + sw, g_wc16 + (size_t)r * K + k0 + q * 8);
        }
        asm volatile("cp.async.commit_group;" ::: "memory");
    };

    ldA(0);
    cpB(0, 0);

    for (int c = 0; c < nchunk; c++) {
        int buf = c & 1;
        stsA();
        asm volatile("cp.async.wait_group 0;" ::: "memory");
        __syncthreads();
        if (c + 1 < nchunk) { ldA(c + 1); cpB(c + 1, buf ^ 1); }

        int Bs = buf ? SM_B1 : SM_B0;
#pragma unroll
        for (int s = 0; s < 4; s++) {
            uint32_t ah[2][4], bh[4][4];
#pragma unroll
            for (int fm = 0; fm < 2; fm++) {
                uint32_t row = (uint32_t)(wm * 32 + fm * 16 + ((lg & 1) << 3) + lr);
                uint32_t kb = (uint32_t)(s * 32 + ((lg >> 1) << 4));
                ldsm_x4(ah[fm], sbase + SM_A0 + SMEM_SWIZZLE_128B(row * 128 + kb));
            }
#pragma unroll
            for (int fn2 = 0; fn2 < 4; fn2++) {
                uint32_t row = (uint32_t)(wn * 64 + fn2 * 16 + ((lg >> 1) << 3) + lr);
                uint32_t kb = (uint32_t)(s * 32 + ((lg & 1) << 4));
                ldsm_x4(bh[fn2], sbase + Bs + SMEM_SWIZZLE_128B(row * 128 + kb));
            }
#pragma unroll
            for (int fm = 0; fm < 2; fm++)
#pragma unroll
                for (int fn2 = 0; fn2 < 4; fn2++)
#pragma unroll
                    for (int nh = 0; nh < 2; nh++)
                        mma_f16(acc[fm][fn2 * 2 + nh], ah[fm],
                                bh[fn2][nh * 2], bh[fn2][nh * 2 + 1]);
        }
        __syncthreads();
    }

    int gq = lane >> 2;
    int tq = lane & 3;
#pragma unroll
    for (int fm = 0; fm < 2; fm++) {
#pragma unroll
        for (int half = 0; half < 2; half++) {
            int row = rowBase + wm * 32 + fm * 16 + half * 8 + gq;
            if (row >= M) continue;
#pragma unroll
            for (int fn = 0; fn < 8; fn++) {
                int col = wn * 64 + fn * 8 + tq * 2;
                *(__half2*)(g_h + (size_t)row * 128 + col) =
                    __floats2half2_rn(acc[fm][fn][half * 2 + 0], acc[fm][fn][half * 2 + 1]);
            }
        }
    }
}

// ---------------------------------------------------------------------------
// Fused gather + GEMM2. One CTA per 128 dst nodes.
// Phase 1: 8 warps gather 128 agg rows (fp16) straight into the smem A tile.
// Phase 2: out[128, 512] = A @ WlT over 4 n-tiles (double-buffered B).
// ---------------------------------------------------------------------------
__global__ __launch_bounds__(256)
void k_gather_gemm2(const float* __restrict__ bc, const float* __restrict__ bias,
                    float* __restrict__ outp, int M) {
    extern __shared__ char smem[];
    constexpr int SM_A = 0;            // 2 chunks of 16KB: k<64 at 0, k>=64 at 16384
    constexpr int SM_B = 32768;        // + buf*32768 + chunk*16384  (total 98304)

    uint32_t sbase = smem_to_u32(smem);
    int tid = threadIdx.x, wid = tid >> 5, lane = tid & 31;
    int rowBase = blockIdx.x * 128;

    // ---- Phase 1: gather ----
    const __half* hlane = g_h + lane * 4;
    int achunk = lane >> 4;                       // 0 or 1 (k<64 / k>=64)
    uint32_t abyte = (uint32_t)((lane & 15) * 8); // 8B per lane within chunk row

    for (int i = 0; i < 16; i++) {
        int r = wid * 16 + i;
        int d = rowBase + r;
        float4 s4 = make_float4(0.f, 0.f, 0.f, 0.f);
        float dinv_d = 0.0f;
        if (d < M) {
            dinv_d = g_dinv[d];
            uint2 hr = *(const uint2*)(hlane + (size_t)d * H_DIM);
            float2 fa = __half22float2(*reinterpret_cast<__half2*>(&hr.x));
            float2 fb = __half22float2(*reinterpret_cast<__half2*>(&hr.y));
            s4 = make_float4(dinv_d * fa.x, dinv_d * fa.y, dinv_d * fb.x, dinv_d * fb.y);

            int beg = g_off[d], end = beg + g_cnt[d];
            for (int base = beg; base < end; base += 32) {
                int idx = base + lane;
                uint32_t esrc = 0u;
                float cfl = 0.0f;
                if (idx < end) {
                    uint2 e = g_edges[idx];
                    esrc = e.x;
                    cfl = __uint_as_float(e.y) * __ldg(&g_dinv[e.x]);
                }
                int cnt = min(32, end - base);
#pragma unroll
                for (int b = 0; b < 32; b += 16) {
                    if (b >= cnt) break;
                    uint2 rv[16];
                    float cf[16];
#pragma unroll
                    for (int j = 0; j < 16; j++) {
                        int s = __shfl_sync(0xFFFFFFFFu, (int)esrc, b + j);
                        cf[j] = __shfl_sync(0xFFFFFFFFu, cfl, b + j);
                        rv[j] = *(const uint2*)(hlane + (size_t)s * H_DIM);
                    }
#pragma unroll
                    for (int j = 0; j < 16; j++) {
                        float2 pa = __half22float2(*reinterpret_cast<__half2*>(&rv[j].x));
                        float2 pb = __half22float2(*reinterpret_cast<__half2*>(&rv[j].y));
                        s4.x = fmaf(cf[j], pa.x, s4.x);
                        s4.y = fmaf(cf[j], pa.y, s4.y);
                        s4.z = fmaf(cf[j], pb.x, s4.z);
                        s4.w = fmaf(cf[j], pb.y, s4.w);
                    }
                }
            }
        }
        float4 bb4 = *(const float4*)(bc + lane * 4);
        float4 acc4 = make_float4(fmaf(s4.x, dinv_d, bb4.x), fmaf(s4.y, dinv_d, bb4.y),
                                  fmaf(s4.z, dinv_d, bb4.z), fmaf(s4.w, dinv_d, bb4.w));
        uint2 st;
        st.x = pack_f16(acc4.x, acc4.y);
        st.y = pack_f16(acc4.z, acc4.w);
        uint32_t sw = SMEM_SWIZZLE_128B((uint32_t)(r * 128) + abyte);
        *(uint2*)(smem + SM_A + achunk * 16384 + sw) = st;
    }
    __syncthreads();

    // ---- Phase 2: GEMM over 4 n-tiles ----
    uint32_t lr = lane & 7, lg = lane >> 3;
    int wm = wid & 3, wn = wid >> 2;
    int gq = lane >> 2, tq = lane & 3;

    auto cpB = [&](int nt, int buf) {
        int bb = SM_B + buf * 32768;
#pragma unroll
        for (int l = 0; l < 8; l++) {
            int t = tid + l * 256;          // 0..2047
            int kc = t >> 10;
            int r = (t >> 3) & 127;
            int q = t & 7;
            uint32_t sw = SMEM_SWIZZLE_128B((uint32_t)(r * 128 + q * 16));
            cp_async16(sbase + bb + kc * 16384 + sw,
                       g_wl16 + (size_t)(nt * 128 + r) * 128 + kc * 64 + q * 8);
        }
        asm volatile("cp.async.commit_group;" ::: "memory");
    };

    cpB(0, 0);

#pragma unroll
    for (int nt = 0; nt < 4; nt++) {
        int buf = nt & 1;
        asm volatile("cp.async.wait_group 0;" ::: "memory");
        __syncthreads();
        if (nt + 1 < 4) cpB(nt + 1, buf ^ 1);

        float acc[2][8][4];
#pragma unroll
        for (int i = 0; i < 2; i++)
#pragma unroll
            for (int j = 0; j < 8; j++)
#pragma unroll
                for (int k = 0; k < 4; k++) acc[i][j][k] = 0.0f;

#pragma unroll
        for (int kc = 0; kc < 2; kc++) {
            int As = SM_A + kc * 16384;
            int Bs = SM_B + buf * 32768 + kc * 16384;
#pragma unroll
            for (int s = 0; s < 4; s++) {
                uint32_t ah[2][4], bh[4][4];
#pragma unroll
                for (int fm = 0; fm < 2; fm++) {
                    uint32_t row = (uint32_t)(wm * 32 + fm * 16 + ((lg & 1) << 3) + lr);
                    uint32_t kb = (uint32_t)(s * 32 + ((lg >> 1) << 4));
                    ldsm_x4(ah[fm], sbase + As + SMEM_SWIZZLE_128B(row * 128 + kb));
                }
#pragma unroll
                for (int fn2 = 0; fn2 < 4; fn2++) {
                    uint32_t row = (uint32_t)(wn * 64 + fn2 * 16 + ((lg >> 1) << 3) + lr);
                    uint32_t kb = (uint32_t)(s * 32 + ((lg & 1) << 4));
                    ldsm_x4(bh[fn2], sbase + Bs + SMEM_SWIZZLE_128B(row * 128 + kb));
                }
#pragma unroll
                for (int fm = 0; fm < 2; fm++)
#pragma unroll
                    for (int fn2 = 0; fn2 < 4; fn2++)
#pragma unroll
                        for (int nh = 0; nh < 2; nh++)
                            mma_f16(acc[fm][fn2 * 2 + nh], ah[fm],
                                    bh[fn2][nh * 2], bh[fn2][nh * 2 + 1]);
            }
        }

        int colBase = nt * 128;
#pragma unroll
        for (int fm = 0; fm < 2; fm++) {
#pragma unroll
            for (int half = 0; half < 2; half++) {
                int row = rowBase + wm * 32 + fm * 16 + half * 8 + gq;
                if (row >= M) continue;
#pragma unroll
                for (int fn = 0; fn < 8; fn++) {
                    int col = colBase + wn * 64 + fn * 8 + tq * 2;
                    float b0 = __ldg(bias + col), b1 = __ldg(bias + col + 1);
                    *(float2*)(outp + (size_t)row * 512 + col) =
                        make_float2(acc[fm][fn][half * 2 + 0] + b0,
                                    acc[fm][fn][half * 2 + 1] + b1);
                }
            }
        }
        __syncthreads();   // protect B buffer reuse (nt+2 overwrites buf)
    }
}

// ---------------------------------------------------------------------------
extern "C" void kernel_launch(void* const* d_in, const int* in_sizes, int n_in,
                              void* d_out, int out_size) {
    const float* x  = (const float*)d_in[0];
    const int*   ei = (const int*)  d_in[1];
    const float* ew = (const float*)d_in[2];
    const float* Wc = (const float*)d_in[3];  // [512,128]
    const float* bc = (const float*)d_in[4];
    const float* Wl = (const float*)d_in[5];  // [128,512]
    const float* bl = (const float*)d_in[6];
    float* out = (float*)d_out;

    int E = in_sizes[2];
    int n = in_sizes[0] / F_INF;
    const int* src = ei;
    const int* dst = ei + E;

    const int SMEM_G1 = 49152;   // A 16K + B 2x16K
    const int SMEM_FU = 98304;   // A 32K + B 2x32K
    cudaFuncSetAttribute(gemm1_f16, cudaFuncAttributeMaxDynamicSharedMemorySize, SMEM_G1);
    cudaFuncSetAttribute(k_gather_gemm2, cudaFuncAttributeMaxDynamicSharedMemorySize, SMEM_FU);

    // One-time side-stream + events (host resources, not device allocations).
    static cudaStream_t s2 = nullptr;
    static cudaEvent_t evFork = nullptr, evJoin = nullptr;
    if (s2 == nullptr) {
        cudaStreamCreateWithFlags(&s2, cudaStreamNonBlocking);
        cudaEventCreateWithFlags(&evFork, cudaEventDisableTiming);
        cudaEventCreateWithFlags(&evJoin, cudaEventDisableTiming);
    }

    // 1) init (deg2 reset + fp16 weight transposes) — root of both branches
    k_init<<<(H_DIM * F_INF + 255) / 256, 256>>>(Wc, Wl, n);

    // Fork: GEMM1 on s2, concurrent with edge prep on the main stream.
    cudaEventRecord(evFork, 0);
    cudaStreamWaitEvent(s2, evFork, 0);
    {
        dim3 grid(1, (n + 127) / 128);
        gemm1_f16<<<grid, 256, SMEM_G1, s2>>>(x, n, F_INF);
    }

    k_deg_accum<<<(E + 255) / 256, 256>>>(dst, ew, E);
    k_dinv_assign<<<(n + 255) / 256, 256>>>(n);
    k_fill<<<(E + 255) / 256, 256>>>(src, dst, ew, E);

    // Join: fused kernel needs g_h (s2) and g_edges/g_off/g_cnt/g_dinv (main)
    cudaEventRecord(evJoin, s2);
    cudaStreamWaitEvent(0, evJoin, 0);

    // Fused gather + GEMM2 -> out
    {
        int blocks = (n + 127) / 128;
        k_gather_gemm2<<<blocks, 256, SMEM_FU>>>(bc, bl, out, n);
    }
}

// round 13
// speedup vs baseline: 1.2637x; 1.2637x over previous
#include <cuda_runtime.h>
#include <cuda_fp16.h>
#include <cstdint>

#define N_NODES 50000
#define F_INF   512
#define H_DIM   128
#define E_MAX   1600000
#define NCHUNKS 4

// ---------------------------------------------------------------------------
// Device scratch
// ---------------------------------------------------------------------------
__device__ __align__(8) float2 g_deg2[N_NODES];   // {sum_w, count}
__device__ float g_dinv[N_NODES];
__device__ int   g_cnt [N_NODES];
__device__ int   g_off [N_NODES];
__device__ int   g_cur [N_NODES];
__device__ int   g_total;
__device__ __align__(16) uint2  g_edges[E_MAX];                    // (src, w) 12.8 MB
__device__ __align__(16) __half g_h   [(size_t)N_NODES * H_DIM];   // 12.8 MB
__device__ __align__(16) __half g_aggh[(size_t)N_NODES * H_DIM];   // 12.8 MB
__device__ __align__(16) __half g_wc16[H_DIM * F_INF];             // Wc^T fp16 [128,512]
__device__ __align__(16) __half g_wl16[F_INF * H_DIM];             // Wl^T fp16 [512,128]

#define SMEM_SWIZZLE_128B(off) ((off) ^ (((off) >> 3) & 0x70))

__device__ __forceinline__ uint32_t smem_to_u32(const void* p) {
    uint32_t a;
    asm("{ .reg .u64 t; cvta.to.shared.u64 t, %1; cvt.u32.u64 %0, t; }"
        : "=r"(a) : "l"(p));
    return a;
}

__device__ __forceinline__ void ldsm_x4(uint32_t* r, uint32_t addr) {
    asm volatile("ldmatrix.sync.aligned.m8n8.x4.shared.b16 {%0,%1,%2,%3}, [%4];"
                 : "=r"(r[0]), "=r"(r[1]), "=r"(r[2]), "=r"(r[3]) : "r"(addr));
}

__device__ __forceinline__ void mma_f16(float* c, const uint32_t* a,
                                        uint32_t b0, uint32_t b1) {
    asm volatile(
        "mma.sync.aligned.m16n8k16.row.col.f32.f16.f16.f32 "
        "{%0,%1,%2,%3}, {%4,%5,%6,%7}, {%8,%9}, {%0,%1,%2,%3};"
        : "+f"(c[0]), "+f"(c[1]), "+f"(c[2]), "+f"(c[3])
        : "r"(a[0]), "r"(a[1]), "r"(a[2]), "r"(a[3]), "r"(b0), "r"(b1));
}

__device__ __forceinline__ uint32_t pack_f16(float x, float y) {
    __half2 p = __floats2half2_rn(x, y);
    return *reinterpret_cast<uint32_t*>(&p);
}

__device__ __forceinline__ void cp_async16(uint32_t smem_addr, const void* gptr) {
    asm volatile("cp.async.cg.shared.global [%0], [%1], 16;"
                 :: "r"(smem_addr), "l"(gptr));
}

// ---------------------------------------------------------------------------
// Init: deg2 reset + transposed fp16 weight conversion
// ---------------------------------------------------------------------------
__global__ void k_init(const float* __restrict__ Wc, const float* __restrict__ Wl, int n) {
    int i = blockIdx.x * blockDim.x + threadIdx.x;
    if (i < n) g_deg2[i] = make_float2(1.0f, 0.0f);
    if (i == 0) g_total = 0;
    if (i < H_DIM * F_INF) {
        int r = i >> 9, c = i & 511;                 // WcT [128,512]
        g_wc16[i] = __float2half(Wc[(size_t)c * H_DIM + r]);
        int r2 = i >> 7, c2 = i & 127;               // WlT [512,128]
        g_wl16[i] = __float2half(Wl[(size_t)c2 * F_INF + r2]);
    }
}

// Single vector reduction per edge: deg += w, cnt += 1
__global__ void k_deg_accum(const int* __restrict__ dst, const float* __restrict__ w, int E) {
    int e = blockIdx.x * blockDim.x + threadIdx.x;
    if (e < E) {
        float2* p = &g_deg2[dst[e]];
        asm volatile("red.global.add.v2.f32 [%0], {%1,%2};"
                     :: "l"(p), "f"(w[e]), "f"(1.0f) : "memory");
    }
}

// dinv + warp-aggregated bin-range assignment
__global__ void k_dinv_assign(int n) {
    int i = blockIdx.x * blockDim.x + threadIdx.x;
    int lane = threadIdx.x & 31;
    int c = 0;
    if (i < n) {
        float2 dg = g_deg2[i];
        g_dinv[i] = (dg.x > 0.0f) ? rsqrtf(dg.x) : 0.0f;
        c = (int)dg.y;
        g_cnt[i] = c;
    }
    int v = c;
#pragma unroll
    for (int o = 1; o < 32; o <<= 1) {
        int t = __shfl_up_sync(0xFFFFFFFFu, v, o);
        if (lane >= o) v += t;
    }
    int warpTotal = __shfl_sync(0xFFFFFFFFu, v, 31);
    int base = 0;
    if (lane == 31 && warpTotal > 0) base = atomicAdd(&g_total, warpTotal);
    base = __shfl_sync(0xFFFFFFFFu, base, 31);
    if (i < n) {
        int off = base + v - c;
        g_off[i] = off;
        g_cur[i] = off;
    }
}

// Fill dst-binned edge list with RAW (src, w)
__global__ void k_fill(const int* __restrict__ src, const int* __restrict__ dst,
                       const float* __restrict__ w, int E) {
    int e = blockIdx.x * blockDim.x + threadIdx.x;
    if (e >= E) return;
    int s = src[e], d = dst[e];
    int pos = atomicAdd(&g_cur[d], 1);
    g_edges[pos] = make_uint2((uint32_t)s, __float_as_uint(__ldg(&w[e])));
}

// ---------------------------------------------------------------------------
// Unified single-pass fp16 GEMM (fp32 accumulate), 128x128 CTA, 8 warps.
// MODE 0: A = x (fp32, converted in-regs), B = g_wc16, K=512 -> g_h fp16
// MODE 1: A = g_aggh (fp16, cp.async),     B = g_wl16, K=128 -> out fp32 + bias
// rowOff: node-row offset of this launch (chunked GEMM2 pipelining).
// ---------------------------------------------------------------------------
template <int MODE>
__global__ __launch_bounds__(256)
void gemm_f16(const float* __restrict__ A32,
              const __half* __restrict__ Bw,
              const float* __restrict__ bias,
              float* __restrict__ outp,
              int M, int K, int rowOff) {
    extern __shared__ char smem[];
    constexpr int SM_A0 = 0, SM_A1 = 16384;
    constexpr int SM_B0 = 32768, SM_B1 = 49152;

    uint32_t sbase = smem_to_u32(smem);
    int tid = threadIdx.x;
    int wid = tid >> 5, lane = tid & 31;
    int wm = wid & 3, wn = wid >> 2;
    int rowBase = rowOff + blockIdx.y * 128;
    int colBase = blockIdx.x * 128;

    float acc[2][8][4];
#pragma unroll
    for (int i = 0; i < 2; i++)
#pragma unroll
        for (int j = 0; j < 8; j++)
#pragma unroll
            for (int k = 0; k < 4; k++) acc[i][j][k] = 0.0f;

    uint32_t lr = lane & 7, lg = lane >> 3;
    int nchunk = K >> 6;

    float4 aR[4][2];
    auto ldA = [&](int c) {
        int k0 = c << 6;
#pragma unroll
        for (int l = 0; l < 4; l++) {
            int t = tid + l * 256;
            int r = t >> 3, q = t & 7;
            int grow = rowBase + r;
            float4 v0 = make_float4(0.f, 0.f, 0.f, 0.f), v1 = v0;
            if (grow < M) {
                const float* ap = A32 + (size_t)grow * K + k0 + q * 8;
                v0 = *(const float4*)ap;
                v1 = *(const float4*)(ap + 4);
            }
            aR[l][0] = v0; aR[l][1] = v1;
        }
    };
    auto stsA = [&]() {
#pragma unroll
        for (int l = 0; l < 4; l++) {
            int t = tid + l * 256;
            int r = t >> 3, q = t & 7;
            float4 v0 = aR[l][0], v1 = aR[l][1];
            uint4 hv;
            hv.x = pack_f16(v0.x, v0.y); hv.y = pack_f16(v0.z, v0.w);
            hv.z = pack_f16(v1.x, v1.y); hv.w = pack_f16(v1.z, v1.w);
            uint32_t sw = SMEM_SWIZZLE_128B((uint32_t)(r * 128 + q * 16));
            *(uint4*)(smem + SM_A0 + sw) = hv;
        }
    };
    auto cpA = [&](int c, int buf) {
        int k0 = c << 6;
        int ab = buf ? SM_A1 : SM_A0;
#pragma unroll
        for (int l = 0; l < 4; l++) {
            int t = tid + l * 256;
            int r = t >> 3, q = t & 7;
            int grow = rowBase + r;
            if (grow >= M) grow = M - 1;
            uint32_t sw = SMEM_SWIZZLE_128B((uint32_t)(r * 128 + q * 16));
            cp_async16(sbase + ab + sw, g_aggh + (size_t)grow * 128 + k0 + q * 8);
        }
    };
    auto cpB = [&](int c, int buf) {
        int k0 = c << 6;
        int bb = buf ? SM_B1 : SM_B0;
#pragma unroll
        for (int l = 0; l < 4; l++) {
            int t = tid + l * 256;
            int r = t >> 3, q = t & 7;
            uint32_t sw = SMEM_SWIZZLE_128B((uint32_t)(r * 128 + q * 16));
            cp_async16(sbase + bb + sw, Bw + (size_t)(colBase + r) * K + k0 + q * 8);
        }
    };

    if (MODE == 0) { ldA(0); }
    else           { cpA(0, 0); }
    cpB(0, 0);
    asm volatile("cp.async.commit_group;" ::: "memory");

    for (int c = 0; c < nchunk; c++) {
        int buf = c & 1;
        if (MODE == 0) stsA();
        asm volatile("cp.async.wait_group 0;" ::: "memory");
        __syncthreads();
        if (c + 1 < nchunk) {
            if (MODE == 0) { ldA(c + 1); }
            else           { cpA(c + 1, buf ^ 1); }
            cpB(c + 1, buf ^ 1);
            asm volatile("cp.async.commit_group;" ::: "memory");
        }

        int As = (MODE == 0) ? SM_A0 : (buf ? SM_A1 : SM_A0);
        int Bs = buf ? SM_B1 : SM_B0;
#pragma unroll
        for (int s = 0; s < 4; s++) {
            uint32_t ah[2][4], bh[4][4];
#pragma unroll
            for (int fm = 0; fm < 2; fm++) {
                uint32_t row = (uint32_t)(wm * 32 + fm * 16 + ((lg & 1) << 3) + lr);
                uint32_t kb = (uint32_t)(s * 32 + ((lg >> 1) << 4));
                ldsm_x4(ah[fm], sbase + As + SMEM_SWIZZLE_128B(row * 128 + kb));
            }
#pragma unroll
            for (int fn2 = 0; fn2 < 4; fn2++) {
                uint32_t row = (uint32_t)(wn * 64 + fn2 * 16 + ((lg >> 1) << 3) + lr);
                uint32_t kb = (uint32_t)(s * 32 + ((lg & 1) << 4));
                ldsm_x4(bh[fn2], sbase + Bs + SMEM_SWIZZLE_128B(row * 128 + kb));
            }
#pragma unroll
            for (int fm = 0; fm < 2; fm++)
#pragma unroll
                for (int fn2 = 0; fn2 < 4; fn2++)
#pragma unroll
                    for (int nh = 0; nh < 2; nh++)
                        mma_f16(acc[fm][fn2 * 2 + nh], ah[fm],
                                bh[fn2][nh * 2], bh[fn2][nh * 2 + 1]);
        }
        __syncthreads();
    }

    int gq = lane >> 2;
    int tq = lane & 3;
#pragma unroll
    for (int fm = 0; fm < 2; fm++) {
#pragma unroll
        for (int half = 0; half < 2; half++) {
            int row = rowBase + wm * 32 + fm * 16 + half * 8 + gq;
            if (row >= M) continue;
#pragma unroll
            for (int fn = 0; fn < 8; fn++) {
                int col = colBase + wn * 64 + fn * 8 + tq * 2;
                float c0 = acc[fm][fn][half * 2 + 0];
                float c1 = acc[fm][fn][half * 2 + 1];
                if (MODE == 0) {
                    *(__half2*)(g_h + (size_t)row * 128 + col) = __floats2half2_rn(c0, c1);
                } else {
                    float b0 = __ldg(bias + col), b1 = __ldg(bias + col + 1);
                    *(float2*)(outp + (size_t)row * 512 + col) = make_float2(c0 + b0, c1 + b1);
                }
            }
        }
    }
}

// ---------------------------------------------------------------------------
// Gather-aggregate for node range [lo, hi): warp per dst, fp16 rows, MLP-16.
//   agg[d] = (sum_e dinv[s]*w*h[s] + dinv_d*h[d]) * dinv_d + b_conv
// ---------------------------------------------------------------------------
__global__ __launch_bounds__(256)
void k_gather(const float* __restrict__ bc, int lo, int hi) {
    int gwarp = lo + ((blockIdx.x * blockDim.x + threadIdx.x) >> 5);
    int lane = threadIdx.x & 31;
    if (gwarp >= hi) return;
    int d = gwarp;
    int beg = g_off[d];
    int end = beg + g_cnt[d];

    const __half* hlane = g_h + lane * 4;

    float dinv_d = g_dinv[d];
    uint2 hr = *(const uint2*)(hlane + (size_t)d * H_DIM);
    float2 fa = __half22float2(*reinterpret_cast<__half2*>(&hr.x));
    float2 fb = __half22float2(*reinterpret_cast<__half2*>(&hr.y));
    float4 s4 = make_float4(dinv_d * fa.x, dinv_d * fa.y, dinv_d * fb.x, dinv_d * fb.y);

    for (int base = beg; base < end; base += 32) {
        int idx = base + lane;
        uint32_t esrc = 0u;
        float cfl = 0.0f;
        if (idx < end) {
            uint2 e = g_edges[idx];
            esrc = e.x;
            cfl = __uint_as_float(e.y) * __ldg(&g_dinv[e.x]);   // dinv[s] * w
        }
        int cnt = min(32, end - base);
#pragma unroll
        for (int b = 0; b < 32; b += 16) {
            if (b >= cnt) break;
            uint2 rv[16];
            float cf[16];
#pragma unroll
            for (int j = 0; j < 16; j++) {
                int s = __shfl_sync(0xFFFFFFFFu, (int)esrc, b + j);
                cf[j] = __shfl_sync(0xFFFFFFFFu, cfl, b + j);
                rv[j] = *(const uint2*)(hlane + (size_t)s * H_DIM);
            }
#pragma unroll
            for (int j = 0; j < 16; j++) {
                float2 pa = __half22float2(*reinterpret_cast<__half2*>(&rv[j].x));
                float2 pb = __half22float2(*reinterpret_cast<__half2*>(&rv[j].y));
                s4.x = fmaf(cf[j], pa.x, s4.x);
                s4.y = fmaf(cf[j], pa.y, s4.y);
                s4.z = fmaf(cf[j], pb.x, s4.z);
                s4.w = fmaf(cf[j], pb.y, s4.w);
            }
        }
    }
    float4 bb = *(const float4*)(bc + lane * 4);
    float4 acc = make_float4(fmaf(s4.x, dinv_d, bb.x), fmaf(s4.y, dinv_d, bb.y),
                             fmaf(s4.z, dinv_d, bb.z), fmaf(s4.w, dinv_d, bb.w));
    uint2 st;
    st.x = pack_f16(acc.x, acc.y);
    st.y = pack_f16(acc.z, acc.w);
    *(uint2*)(g_aggh + (size_t)d * H_DIM + lane * 4) = st;
}

// ---------------------------------------------------------------------------
extern "C" void kernel_launch(void* const* d_in, const int* in_sizes, int n_in,
                              void* d_out, int out_size) {
    const float* x  = (const float*)d_in[0];
    const int*   ei = (const int*)  d_in[1];
    const float* ew = (const float*)d_in[2];
    const float* Wc = (const float*)d_in[3];  // [512,128]
    const float* bc = (const float*)d_in[4];
    const float* Wl = (const float*)d_in[5];  // [128,512]
    const float* bl = (const float*)d_in[6];
    float* out = (float*)d_out;

    int E = in_sizes[2];
    int n = in_sizes[0] / F_INF;
    const int* src = ei;
    const int* dst = ei + E;

    const int SMEM_BYTES = 65536;
    cudaFuncSetAttribute(gemm_f16<0>, cudaFuncAttributeMaxDynamicSharedMemorySize, SMEM_BYTES);
    cudaFuncSetAttribute(gemm_f16<1>, cudaFuncAttributeMaxDynamicSharedMemorySize, SMEM_BYTES);

    __half *wc16, *wl16;
    cudaGetSymbolAddress((void**)&wc16, g_wc16);
    cudaGetSymbolAddress((void**)&wl16, g_wl16);

    // One-time side-stream + events (host resources, not device allocations).
    static cudaStream_t s2 = nullptr;
    static cudaEvent_t evFork = nullptr, evJoin = nullptr, evEnd = nullptr;
    static cudaEvent_t evChunk[NCHUNKS];
    if (s2 == nullptr) {
        cudaStreamCreateWithFlags(&s2, cudaStreamNonBlocking);
        cudaEventCreateWithFlags(&evFork, cudaEventDisableTiming);
        cudaEventCreateWithFlags(&evJoin, cudaEventDisableTiming);
        cudaEventCreateWithFlags(&evEnd, cudaEventDisableTiming);
        for (int c = 0; c < NCHUNKS; c++)
            cudaEventCreateWithFlags(&evChunk[c], cudaEventDisableTiming);
    }

    // 1) init (deg2 reset + fp16 weight transposes) — root of both branches
    k_init<<<(H_DIM * F_INF + 255) / 256, 256>>>(Wc, Wl, n);

    // Fork: GEMM1 on s2, concurrent with edge prep on the main stream.
    cudaEventRecord(evFork, 0);
    cudaStreamWaitEvent(s2, evFork, 0);
    {
        dim3 grid(1, (n + 127) / 128);
        gemm_f16<0><<<grid, 256, SMEM_BYTES, s2>>>(x, wc16, nullptr, nullptr, n, F_INF, 0);
    }

    // Edge-prep branch on the main stream
    k_deg_accum<<<(E + 255) / 256, 256>>>(dst, ew, E);
    k_dinv_assign<<<(n + 255) / 256, 256>>>(n);
    k_fill<<<(E + 255) / 256, 256>>>(src, dst, ew, E);

    // Join: gather needs g_h (s2) and g_edges/g_off/g_cnt/g_dinv (main)
    cudaEventRecord(evJoin, s2);
    cudaStreamWaitEvent(0, evJoin, 0);

    // Chunked gather (main) -> GEMM2 (s2) pipeline.
    int totalBlocks = (n + 127) / 128;                 // 128-row blocks
    int blocksPerChunk = (totalBlocks + NCHUNKS - 1) / NCHUNKS;
    for (int c = 0; c < NCHUNKS; c++) {
        int b0 = c * blocksPerChunk;
        if (b0 >= totalBlocks) break;
        int nb = min(blocksPerChunk, totalBlocks - b0);
        int lo = b0 * 128;
        int hi = min(n, (b0 + nb) * 128);

        // gather chunk on main stream (full occupancy, 0 smem)
        int nwarps = hi - lo;
        int gblocks = (nwarps * 32 + 255) / 256;
        k_gather<<<gblocks, 256>>>(bc, lo, hi);
        cudaEventRecord(evChunk[c], 0);

        // GEMM2 chunk on s2, overlapping the next gather chunk
        cudaStreamWaitEvent(s2, evChunk[c], 0);
        dim3 grid(F_INF / 128, nb);
        gemm_f16<1><<<grid, 256, SMEM_BYTES, s2>>>(nullptr, wl16, bl, out, n, H_DIM, lo);
    }

    // Join s2 back into the main stream before returning.
    cudaEventRecord(evEnd, s2);
    cudaStreamWaitEvent(0, evEnd, 0);
}

// round 14
// speedup vs baseline: 1.4827x; 1.1734x over previous
#include <cuda_runtime.h>
#include <cuda_fp16.h>
#include <cstdint>

#define N_NODES 50000
#define F_INF   512
#define H_DIM   128
#define E_MAX   1600000

// ---------------------------------------------------------------------------
// Device scratch
// ---------------------------------------------------------------------------
__device__ __align__(8) float2 g_deg2[N_NODES];   // {sum_w, count}
__device__ float g_dinv[N_NODES];
__device__ int   g_cnt [N_NODES];
__device__ int   g_off [N_NODES];
__device__ int   g_cur [N_NODES];
__device__ int   g_total;
__device__ __align__(16) uint2  g_edges[E_MAX];                    // (src, coef) 12.8 MB
__device__ __align__(16) __half g_h   [(size_t)N_NODES * H_DIM];   // 12.8 MB
__device__ __align__(16) __half g_aggh[(size_t)N_NODES * H_DIM];   // 12.8 MB
__device__ __align__(16) __half g_wc16[H_DIM * F_INF];             // Wc^T fp16 [128,512]
__device__ __align__(16) __half g_wl16[F_INF * H_DIM];             // Wl^T fp16 [512,128]

#define SMEM_SWIZZLE_128B(off) ((off) ^ (((off) >> 3) & 0x70))

__device__ __forceinline__ uint32_t smem_to_u32(const void* p) {
    uint32_t a;
    asm("{ .reg .u64 t; cvta.to.shared.u64 t, %1; cvt.u32.u64 %0, t; }"
        : "=r"(a) : "l"(p));
    return a;
}

__device__ __forceinline__ void ldsm_x4(uint32_t* r, uint32_t addr) {
    asm volatile("ldmatrix.sync.aligned.m8n8.x4.shared.b16 {%0,%1,%2,%3}, [%4];"
                 : "=r"(r[0]), "=r"(r[1]), "=r"(r[2]), "=r"(r[3]) : "r"(addr));
}

__device__ __forceinline__ void mma_f16(float* c, const uint32_t* a,
                                        uint32_t b0, uint32_t b1) {
    asm volatile(
        "mma.sync.aligned.m16n8k16.row.col.f32.f16.f16.f32 "
        "{%0,%1,%2,%3}, {%4,%5,%6,%7}, {%8,%9}, {%0,%1,%2,%3};"
        : "+f"(c[0]), "+f"(c[1]), "+f"(c[2]), "+f"(c[3])
        : "r"(a[0]), "r"(a[1]), "r"(a[2]), "r"(a[3]), "r"(b0), "r"(b1));
}

__device__ __forceinline__ uint32_t pack_f16(float x, float y) {
    __half2 p = __floats2half2_rn(x, y);
    return *reinterpret_cast<uint32_t*>(&p);
}

__device__ __forceinline__ void cp_async16(uint32_t smem_addr, const void* gptr) {
    asm volatile("cp.async.cg.shared.global [%0], [%1], 16;"
                 :: "r"(smem_addr), "l"(gptr));
}

// ---------------------------------------------------------------------------
// Init: deg2 reset + transposed fp16 weight conversion
// ---------------------------------------------------------------------------
__global__ void k_init(const float* __restrict__ Wc, const float* __restrict__ Wl, int n) {
    int i = blockIdx.x * blockDim.x + threadIdx.x;
    if (i < n) g_deg2[i] = make_float2(1.0f, 0.0f);
    if (i == 0) g_total = 0;
    if (i < H_DIM * F_INF) {
        int r = i >> 9, c = i & 511;                 // WcT [128,512]
        g_wc16[i] = __float2half(Wc[(size_t)c * H_DIM + r]);
        int r2 = i >> 7, c2 = i & 127;               // WlT [512,128]
        g_wl16[i] = __float2half(Wl[(size_t)c2 * F_INF + r2]);
    }
}

// Single vector reduction per edge: deg += w, cnt += 1
__global__ void k_deg_accum(const int* __restrict__ dst, const float* __restrict__ w, int E) {
    int e = blockIdx.x * blockDim.x + threadIdx.x;
    if (e < E) {
        float2* p = &g_deg2[dst[e]];
        asm volatile("red.global.add.v2.f32 [%0], {%1,%2};"
                     :: "l"(p), "f"(w[e]), "f"(1.0f) : "memory");
    }
}

// dinv + warp-aggregated bin-range assignment
__global__ void k_dinv_assign(int n) {
    int i = blockIdx.x * blockDim.x + threadIdx.x;
    int lane = threadIdx.x & 31;
    int c = 0;
    if (i < n) {
        float2 dg = g_deg2[i];
        g_dinv[i] = (dg.x > 0.0f) ? rsqrtf(dg.x) : 0.0f;
        c = (int)dg.y;
        g_cnt[i] = c;
    }
    int v = c;
#pragma unroll
    for (int o = 1; o < 32; o <<= 1) {
        int t = __shfl_up_sync(0xFFFFFFFFu, v, o);
        if (lane >= o) v += t;
    }
    int warpTotal = __shfl_sync(0xFFFFFFFFu, v, 31);
    int base = 0;
    if (lane == 31 && warpTotal > 0) base = atomicAdd(&g_total, warpTotal);
    base = __shfl_sync(0xFFFFFFFFu, base, 31);
    if (i < n) {
        int off = base + v - c;
        g_off[i] = off;
        g_cur[i] = off;
    }
}

// Fill dst-binned edge list with precomputed coef = dinv[s]*w*dinv[d]
// (runs in the fork branch, hidden behind GEMM1 -> keep gather lean instead)
__global__ void k_fill(const int* __restrict__ src, const int* __restrict__ dst,
                       const float* __restrict__ w, int E) {
    int e = blockIdx.x * blockDim.x + threadIdx.x;
    if (e >= E) return;
    int s = src[e], d = dst[e];
    float coef = g_dinv[s] * __ldg(&w[e]) * g_dinv[d];
    int pos = atomicAdd(&g_cur[d], 1);
    g_edges[pos] = make_uint2((uint32_t)s, __float_as_uint(coef));
}

// ---------------------------------------------------------------------------
// Unified single-pass fp16 GEMM (fp32 accumulate), 128x128 CTA, 8 warps.
// MODE 0: A = x (fp32, __ldcs streaming), B = g_wc16, K=512 -> g_h fp16
// MODE 1: A = g_aggh (fp16, cp.async),    B = g_wl16, K=128 -> out fp32 (__stcs)
// ---------------------------------------------------------------------------
template <int MODE>
__global__ __launch_bounds__(256)
void gemm_f16(const float* __restrict__ A32,
              const __half* __restrict__ Bw,
              const float* __restrict__ bias,
              float* __restrict__ outp,
              int M, int K) {
    extern __shared__ char smem[];
    constexpr int SM_A0 = 0, SM_A1 = 16384;
    constexpr int SM_B0 = 32768, SM_B1 = 49152;

    uint32_t sbase = smem_to_u32(smem);
    int tid = threadIdx.x;
    int wid = tid >> 5, lane = tid & 31;
    int wm = wid & 3, wn = wid >> 2;
    int rowBase = blockIdx.y * 128;
    int colBase = blockIdx.x * 128;

    float acc[2][8][4];
#pragma unroll
    for (int i = 0; i < 2; i++)
#pragma unroll
        for (int j = 0; j < 8; j++)
#pragma unroll
            for (int k = 0; k < 4; k++) acc[i][j][k] = 0.0f;

    uint32_t lr = lane & 7, lg = lane >> 3;
    int nchunk = K >> 6;

    float4 aR[4][2];
    auto ldA = [&](int c) {
        int k0 = c << 6;
#pragma unroll
        for (int l = 0; l < 4; l++) {
            int t = tid + l * 256;
            int r = t >> 3, q = t & 7;
            int grow = rowBase + r;
            float4 v0 = make_float4(0.f, 0.f, 0.f, 0.f), v1 = v0;
            if (grow < M) {
                const float4* ap = (const float4*)(A32 + (size_t)grow * K + k0 + q * 8);
                v0 = __ldcs(ap);          // streaming: x is read exactly once
                v1 = __ldcs(ap + 1);
            }
            aR[l][0] = v0; aR[l][1] = v1;
        }
    };
    auto stsA = [&]() {
#pragma unroll
        for (int l = 0; l < 4; l++) {
            int t = tid + l * 256;
            int r = t >> 3, q = t & 7;
            float4 v0 = aR[l][0], v1 = aR[l][1];
            uint4 hv;
            hv.x = pack_f16(v0.x, v0.y); hv.y = pack_f16(v0.z, v0.w);
            hv.z = pack_f16(v1.x, v1.y); hv.w = pack_f16(v1.z, v1.w);
            uint32_t sw = SMEM_SWIZZLE_128B((uint32_t)(r * 128 + q * 16));
            *(uint4*)(smem + SM_A0 + sw) = hv;
        }
    };
    auto cpA = [&](int c, int buf) {
        int k0 = c << 6;
        int ab = buf ? SM_A1 : SM_A0;
#pragma unroll
        for (int l = 0; l < 4; l++) {
            int t = tid + l * 256;
            int r = t >> 3, q = t & 7;
            int grow = rowBase + r;
            if (grow >= M) grow = M - 1;
            uint32_t sw = SMEM_SWIZZLE_128B((uint32_t)(r * 128 + q * 16));
            cp_async16(sbase + ab + sw, g_aggh + (size_t)grow * 128 + k0 + q * 8);
        }
    };
    auto cpB = [&](int c, int buf) {
        int k0 = c << 6;
        int bb = buf ? SM_B1 : SM_B0;
#pragma unroll
        for (int l = 0; l < 4; l++) {
            int t = tid + l * 256;
            int r = t >> 3, q = t & 7;
            uint32_t sw = SMEM_SWIZZLE_128B((uint32_t)(r * 128 + q * 16));
            cp_async16(sbase + bb + sw, Bw + (size_t)(colBase + r) * K + k0 + q * 8);
        }
    };

    if (MODE == 0) { ldA(0); }
    else           { cpA(0, 0); }
    cpB(0, 0);
    asm volatile("cp.async.commit_group;" ::: "memory");

    for (int c = 0; c < nchunk; c++) {
        int buf = c & 1;
        if (MODE == 0) stsA();
        asm volatile("cp.async.wait_group 0;" ::: "memory");
        __syncthreads();
        if (c + 1 < nchunk) {
            if (MODE == 0) { ldA(c + 1); }
            else           { cpA(c + 1, buf ^ 1); }
            cpB(c + 1, buf ^ 1);
            asm volatile("cp.async.commit_group;" ::: "memory");
        }

        int As = (MODE == 0) ? SM_A0 : (buf ? SM_A1 : SM_A0);
        int Bs = buf ? SM_B1 : SM_B0;
#pragma unroll
        for (int s = 0; s < 4; s++) {
            uint32_t ah[2][4], bh[4][4];
#pragma unroll
            for (int fm = 0; fm < 2; fm++) {
                uint32_t row = (uint32_t)(wm * 32 + fm * 16 + ((lg & 1) << 3) + lr);
                uint32_t kb = (uint32_t)(s * 32 + ((lg >> 1) << 4));
                ldsm_x4(ah[fm], sbase + As + SMEM_SWIZZLE_128B(row * 128 + kb));
            }
#pragma unroll
            for (int fn2 = 0; fn2 < 4; fn2++) {
                uint32_t row = (uint32_t)(wn * 64 + fn2 * 16 + ((lg >> 1) << 3) + lr);
                uint32_t kb = (uint32_t)(s * 32 + ((lg & 1) << 4));
                ldsm_x4(bh[fn2], sbase + Bs + SMEM_SWIZZLE_128B(row * 128 + kb));
            }
#pragma unroll
            for (int fm = 0; fm < 2; fm++)
#pragma unroll
                for (int fn2 = 0; fn2 < 4; fn2++)
#pragma unroll
                    for (int nh = 0; nh < 2; nh++)
                        mma_f16(acc[fm][fn2 * 2 + nh], ah[fm],
                                bh[fn2][nh * 2], bh[fn2][nh * 2 + 1]);
        }
        __syncthreads();
    }

    int gq = lane >> 2;
    int tq = lane & 3;
#pragma unroll
    for (int fm = 0; fm < 2; fm++) {
#pragma unroll
        for (int half = 0; half < 2; half++) {
            int row = rowBase + wm * 32 + fm * 16 + half * 8 + gq;
            if (row >= M) continue;
#pragma unroll
            for (int fn = 0; fn < 8; fn++) {
                int col = colBase + wn * 64 + fn * 8 + tq * 2;
                float c0 = acc[fm][fn][half * 2 + 0];
                float c1 = acc[fm][fn][half * 2 + 1];
                if (MODE == 0) {
                    *(__half2*)(g_h + (size_t)row * 128 + col) = __floats2half2_rn(c0, c1);
                } else {
                    float b0 = __ldg(bias + col), b1 = __ldg(bias + col + 1);
                    // streaming store: out is written once, never re-read;
                    // keep L2 for g_h / g_aggh instead
                    __stcs((float2*)(outp + (size_t)row * 512 + col),
                           make_float2(c0 + b0, c1 + b1));
                }
            }
        }
    }
}

// ---------------------------------------------------------------------------
// Gather-aggregate: warp per dst node, fp16 rows, MLP-16,
// edge-batch prefetch (next batch's coalesced load issued before processing).
//   agg[d] = b_conv + dinv_d^2*h[d] + sum_e coef_e*h[src_e]   -> g_aggh fp16
// ---------------------------------------------------------------------------
__global__ __launch_bounds__(256)
void k_gather(const float* __restrict__ bc, int n) {
    int gwarp = (blockIdx.x * blockDim.x + threadIdx.x) >> 5;
    int lane = threadIdx.x & 31;
    if (gwarp >= n) return;
    int d = gwarp;
    int beg = g_off[d];
    int end = beg + g_cnt[d];

    const __half* hlane = g_h + lane * 4;

    float di = g_dinv[d];
    float sc = di * di;
    float4 bb = *(const float4*)(bc + lane * 4);
    uint2 hr = *(const uint2*)(hlane + (size_t)d * H_DIM);
    float2 fa = __half22float2(*reinterpret_cast<__half2*>(&hr.x));
    float2 fb = __half22float2(*reinterpret_cast<__half2*>(&hr.y));
    float4 acc = make_float4(fmaf(sc, fa.x, bb.x), fmaf(sc, fa.y, bb.y),
                             fmaf(sc, fb.x, bb.z), fmaf(sc, fb.y, bb.w));

    // prefetch first edge batch
    uint2 e = make_uint2(0u, 0u);
    if (beg + lane < end) e = g_edges[beg + lane];

    for (int base = beg; base < end; base += 32) {
        // prefetch next batch while processing this one
        uint2 eNext = make_uint2(0u, 0u);
        int nb = base + 32;
        if (nb < end && nb + lane < end) eNext = g_edges[nb + lane];

        int cnt = min(32, end - base);
#pragma unroll
        for (int b = 0; b < 32; b += 16) {
            if (b >= cnt) break;
            uint2 rv[16];
            float cf[16];
#pragma unroll
            for (int j = 0; j < 16; j++) {
                int s = __shfl_sync(0xFFFFFFFFu, (int)e.x, b + j);
                cf[j] = __shfl_sync(0xFFFFFFFFu, __uint_as_float(e.y), b + j);
                rv[j] = *(const uint2*)(hlane + (size_t)s * H_DIM);
            }
#pragma unroll
            for (int j = 0; j < 16; j++) {
                float2 pa = __half22float2(*reinterpret_cast<__half2*>(&rv[j].x));
                float2 pb = __half22float2(*reinterpret_cast<__half2*>(&rv[j].y));
                acc.x = fmaf(cf[j], pa.x, acc.x);
                acc.y = fmaf(cf[j], pa.y, acc.y);
                acc.z = fmaf(cf[j], pb.x, acc.z);
                acc.w = fmaf(cf[j], pb.y, acc.w);
            }
        }
        e = eNext;
    }
    uint2 st;
    st.x = pack_f16(acc.x, acc.y);
    st.y = pack_f16(acc.z, acc.w);
    *(uint2*)(g_aggh + (size_t)d * H_DIM + lane * 4) = st;
}

// ---------------------------------------------------------------------------
extern "C" void kernel_launch(void* const* d_in, const int* in_sizes, int n_in,
                              void* d_out, int out_size) {
    const float* x  = (const float*)d_in[0];
    const int*   ei = (const int*)  d_in[1];
    const float* ew = (const float*)d_in[2];
    const float* Wc = (const float*)d_in[3];  // [512,128]
    const float* bc = (const float*)d_in[4];
    const float* Wl = (const float*)d_in[5];  // [128,512]
    const float* bl = (const float*)d_in[6];
    float* out = (float*)d_out;

    int E = in_sizes[2];
    int n = in_sizes[0] / F_INF;
    const int* src = ei;
    const int* dst = ei + E;

    const int SMEM_BYTES = 65536;
    cudaFuncSetAttribute(gemm_f16<0>, cudaFuncAttributeMaxDynamicSharedMemorySize, SMEM_BYTES);
    cudaFuncSetAttribute(gemm_f16<1>, cudaFuncAttributeMaxDynamicSharedMemorySize, SMEM_BYTES);

    __half *wc16, *wl16;
    cudaGetSymbolAddress((void**)&wc16, g_wc16);
    cudaGetSymbolAddress((void**)&wl16, g_wl16);

    // One-time side-stream + events (host resources, not device allocations).
    static cudaStream_t s2 = nullptr;
    static cudaEvent_t evFork = nullptr, evJoin = nullptr;
    if (s2 == nullptr) {
        cudaStreamCreateWithFlags(&s2, cudaStreamNonBlocking);
        cudaEventCreateWithFlags(&evFork, cudaEventDisableTiming);
        cudaEventCreateWithFlags(&evJoin, cudaEventDisableTiming);
    }

    // 1) init (deg2 reset + fp16 weight transposes) — root of both branches
    k_init<<<(H_DIM * F_INF + 255) / 256, 256>>>(Wc, Wl, n);

    // Fork: GEMM1 (needs only x, wc16) runs on s2 concurrently with edge prep.
    cudaEventRecord(evFork, 0);
    cudaStreamWaitEvent(s2, evFork, 0);
    {
        dim3 grid(1, (n + 127) / 128);
        gemm_f16<0><<<grid, 256, SMEM_BYTES, s2>>>(x, wc16, nullptr, nullptr, n, F_INF);
    }

    // Edge-prep branch on the main stream
    k_deg_accum<<<(E + 255) / 256, 256>>>(dst, ew, E);
    k_dinv_assign<<<(n + 255) / 256, 256>>>(n);
    k_fill<<<(E + 255) / 256, 256>>>(src, dst, ew, E);

    // Join: gather needs both g_h (s2) and g_edges/g_off/g_cnt (main)
    cudaEventRecord(evJoin, s2);
    cudaStreamWaitEvent(0, evJoin, 0);

    // gather-aggregate -> fp16 agg
    {
        int blocks = (n * 32 + 255) / 256;
        k_gather<<<blocks, 256>>>(bc, n);
    }

    // GEMM2: out = agg @ Wl + b_lin
    {
        dim3 grid(F_INF / 128, (n + 127) / 128);
        gemm_f16<1><<<grid, 256, SMEM_BYTES>>>(nullptr, wl16, bl, out, n, H_DIM);
    }
}

// round 15
// speedup vs baseline: 1.4853x; 1.0017x over previous
#include <cuda_runtime.h>
#include <cuda_fp16.h>
#include <cstdint>

#define N_NODES 50000
#define F_INF   512
#define H_DIM   128
#define E_MAX   1600000

// ---------------------------------------------------------------------------
// Device scratch
// ---------------------------------------------------------------------------
__device__ __align__(8) float2 g_deg2[N_NODES];   // {sum_w, count}
__device__ float g_dinv[N_NODES];
__device__ int   g_cnt [N_NODES];
__device__ int   g_off [N_NODES];
__device__ int   g_cur [N_NODES];
__device__ int   g_total;
__device__ __align__(16) uint32_t g_edges[E_MAX];                  // (src<<16)|half(w) 6.4 MB
__device__ __align__(16) __half g_h   [(size_t)N_NODES * H_DIM];   // 12.8 MB
__device__ __align__(16) __half g_aggh[(size_t)N_NODES * H_DIM];   // 12.8 MB
__device__ __align__(16) __half g_wc16[H_DIM * F_INF];             // Wc^T fp16 [128,512]
__device__ __align__(16) __half g_wl16[F_INF * H_DIM];             // Wl^T fp16 [512,128]

#define SMEM_SWIZZLE_128B(off) ((off) ^ (((off) >> 3) & 0x70))

__device__ __forceinline__ uint32_t smem_to_u32(const void* p) {
    uint32_t a;
    asm("{ .reg .u64 t; cvta.to.shared.u64 t, %1; cvt.u32.u64 %0, t; }"
        : "=r"(a) : "l"(p));
    return a;
}

__device__ __forceinline__ void ldsm_x4(uint32_t* r, uint32_t addr) {
    asm volatile("ldmatrix.sync.aligned.m8n8.x4.shared.b16 {%0,%1,%2,%3}, [%4];"
                 : "=r"(r[0]), "=r"(r[1]), "=r"(r[2]), "=r"(r[3]) : "r"(addr));
}

__device__ __forceinline__ void mma_f16(float* c, const uint32_t* a,
                                        uint32_t b0, uint32_t b1) {
    asm volatile(
        "mma.sync.aligned.m16n8k16.row.col.f32.f16.f16.f32 "
        "{%0,%1,%2,%3}, {%4,%5,%6,%7}, {%8,%9}, {%0,%1,%2,%3};"
        : "+f"(c[0]), "+f"(c[1]), "+f"(c[2]), "+f"(c[3])
        : "r"(a[0]), "r"(a[1]), "r"(a[2]), "r"(a[3]), "r"(b0), "r"(b1));
}

__device__ __forceinline__ uint32_t pack_f16(float x, float y) {
    __half2 p = __floats2half2_rn(x, y);
    return *reinterpret_cast<uint32_t*>(&p);
}

__device__ __forceinline__ void cp_async16(uint32_t smem_addr, const void* gptr) {
    asm volatile("cp.async.cg.shared.global [%0], [%1], 16;"
                 :: "r"(smem_addr), "l"(gptr));
}

// ---------------------------------------------------------------------------
// Init: deg2 reset + transposed fp16 weight conversion
// ---------------------------------------------------------------------------
__global__ void k_init(const float* __restrict__ Wc, const float* __restrict__ Wl, int n) {
    int i = blockIdx.x * blockDim.x + threadIdx.x;
    if (i < n) g_deg2[i] = make_float2(1.0f, 0.0f);
    if (i == 0) g_total = 0;
    if (i < H_DIM * F_INF) {
        int r = i >> 9, c = i & 511;                 // WcT [128,512]
        g_wc16[i] = __float2half(Wc[(size_t)c * H_DIM + r]);
        int r2 = i >> 7, c2 = i & 127;               // WlT [512,128]
        g_wl16[i] = __float2half(Wl[(size_t)c2 * F_INF + r2]);
    }
}

// Single vector reduction per edge: deg += w, cnt += 1
__global__ void k_deg_accum(const int* __restrict__ dst, const float* __restrict__ w, int E) {
    int e = blockIdx.x * blockDim.x + threadIdx.x;
    if (e < E) {
        float2* p = &g_deg2[dst[e]];
        asm volatile("red.global.add.v2.f32 [%0], {%1,%2};"
                     :: "l"(p), "f"(w[e]), "f"(1.0f) : "memory");
    }
}

// dinv + warp-aggregated bin-range assignment
__global__ void k_dinv_assign(int n) {
    int i = blockIdx.x * blockDim.x + threadIdx.x;
    int lane = threadIdx.x & 31;
    int c = 0;
    if (i < n) {
        float2 dg = g_deg2[i];
        g_dinv[i] = (dg.x > 0.0f) ? rsqrtf(dg.x) : 0.0f;
        c = (int)dg.y;
        g_cnt[i] = c;
    }
    int v = c;
#pragma unroll
    for (int o = 1; o < 32; o <<= 1) {
        int t = __shfl_up_sync(0xFFFFFFFFu, v, o);
        if (lane >= o) v += t;
    }
    int warpTotal = __shfl_sync(0xFFFFFFFFu, v, 31);
    int base = 0;
    if (lane == 31 && warpTotal > 0) base = atomicAdd(&g_total, warpTotal);
    base = __shfl_sync(0xFFFFFFFFu, base, 31);
    if (i < n) {
        int off = base + v - c;
        g_off[i] = off;
        g_cur[i] = off;
    }
}

// Fill dst-binned edge list: packed 4B record (src<<16 | fp16(w)). No dinv reads.
__global__ void k_fill(const int* __restrict__ src, const int* __restrict__ dst,
                       const float* __restrict__ w, int E) {
    int e = blockIdx.x * blockDim.x + threadIdx.x;
    if (e >= E) return;
    int s = src[e], d = dst[e];
    uint32_t rec = ((uint32_t)s << 16) |
                   (uint32_t)__half_as_ushort(__float2half(__ldg(&w[e])));
    int pos = atomicAdd(&g_cur[d], 1);
    g_edges[pos] = rec;
}

// ---------------------------------------------------------------------------
// Unified single-pass fp16 GEMM (fp32 accumulate), 128x128 CTA, 8 warps.
// MODE 0: A = x (fp32, __ldcs streaming), B = g_wc16, K=512 -> g_h fp16
// MODE 1: A = g_aggh (fp16, cp.async),    B = g_wl16, K=128 -> out fp32 (__stcs)
// ---------------------------------------------------------------------------
template <int MODE>
__global__ __launch_bounds__(256)
void gemm_f16(const float* __restrict__ A32,
              const __half* __restrict__ Bw,
              const float* __restrict__ bias,
              float* __restrict__ outp,
              int M, int K) {
    extern __shared__ char smem[];
    constexpr int SM_A0 = 0, SM_A1 = 16384;
    constexpr int SM_B0 = 32768, SM_B1 = 49152;

    uint32_t sbase = smem_to_u32(smem);
    int tid = threadIdx.x;
    int wid = tid >> 5, lane = tid & 31;
    int wm = wid & 3, wn = wid >> 2;
    int rowBase = blockIdx.y * 128;
    int colBase = blockIdx.x * 128;

    float acc[2][8][4];
#pragma unroll
    for (int i = 0; i < 2; i++)
#pragma unroll
        for (int j = 0; j < 8; j++)
#pragma unroll
            for (int k = 0; k < 4; k++) acc[i][j][k] = 0.0f;

    uint32_t lr = lane & 7, lg = lane >> 3;
    int nchunk = K >> 6;

    float4 aR[4][2];
    auto ldA = [&](int c) {
        int k0 = c << 6;
#pragma unroll
        for (int l = 0; l < 4; l++) {
            int t = tid + l * 256;
            int r = t >> 3, q = t & 7;
            int grow = rowBase + r;
            float4 v0 = make_float4(0.f, 0.f, 0.f, 0.f), v1 = v0;
            if (grow < M) {
                const float4* ap = (const float4*)(A32 + (size_t)grow * K + k0 + q * 8);
                v0 = __ldcs(ap);          // streaming: x is read exactly once
                v1 = __ldcs(ap + 1);
            }
            aR[l][0] = v0; aR[l][1] = v1;
        }
    };
    auto stsA = [&]() {
#pragma unroll
        for (int l = 0; l < 4; l++) {
            int t = tid + l * 256;
            int r = t >> 3, q = t & 7;
            float4 v0 = aR[l][0], v1 = aR[l][1];
            uint4 hv;
            hv.x = pack_f16(v0.x, v0.y); hv.y = pack_f16(v0.z, v0.w);
            hv.z = pack_f16(v1.x, v1.y); hv.w = pack_f16(v1.z, v1.w);
            uint32_t sw = SMEM_SWIZZLE_128B((uint32_t)(r * 128 + q * 16));
            *(uint4*)(smem + SM_A0 + sw) = hv;
        }
    };
    auto cpA = [&](int c, int buf) {
        int k0 = c << 6;
        int ab = buf ? SM_A1 : SM_A0;
#pragma unroll
        for (int l = 0; l < 4; l++) {
            int t = tid + l * 256;
            int r = t >> 3, q = t & 7;
            int grow = rowBase + r;
            if (grow >= M) grow = M - 1;
            uint32_t sw = SMEM_SWIZZLE_128B((uint32_t)(r * 128 + q * 16));
            cp_async16(sbase + ab + sw, g_aggh + (size_t)grow * 128 + k0 + q * 8);
        }
    };
    auto cpB = [&](int c, int buf) {
        int k0 = c << 6;
        int bb = buf ? SM_B1 : SM_B0;
#pragma unroll
        for (int l = 0; l < 4; l++) {
            int t = tid + l * 256;
            int r = t >> 3, q = t & 7;
            uint32_t sw = SMEM_SWIZZLE_128B((uint32_t)(r * 128 + q * 16));
            cp_async16(sbase + bb + sw, Bw + (size_t)(colBase + r) * K + k0 + q * 8);
        }
    };

    if (MODE == 0) { ldA(0); }
    else           { cpA(0, 0); }
    cpB(0, 0);
    asm volatile("cp.async.commit_group;" ::: "memory");

    for (int c = 0; c < nchunk; c++) {
        int buf = c & 1;
        if (MODE == 0) stsA();
        asm volatile("cp.async.wait_group 0;" ::: "memory");
        __syncthreads();
        if (c + 1 < nchunk) {
            if (MODE == 0) { ldA(c + 1); }
            else           { cpA(c + 1, buf ^ 1); }
            cpB(c + 1, buf ^ 1);
            asm volatile("cp.async.commit_group;" ::: "memory");
        }

        int As = (MODE == 0) ? SM_A0 : (buf ? SM_A1 : SM_A0);
        int Bs = buf ? SM_B1 : SM_B0;
#pragma unroll
        for (int s = 0; s < 4; s++) {
            uint32_t ah[2][4], bh[4][4];
#pragma unroll
            for (int fm = 0; fm < 2; fm++) {
                uint32_t row = (uint32_t)(wm * 32 + fm * 16 + ((lg & 1) << 3) + lr);
                uint32_t kb = (uint32_t)(s * 32 + ((lg >> 1) << 4));
                ldsm_x4(ah[fm], sbase + As + SMEM_SWIZZLE_128B(row * 128 + kb));
            }
#pragma unroll
            for (int fn2 = 0; fn2 < 4; fn2++) {
                uint32_t row = (uint32_t)(wn * 64 + fn2 * 16 + ((lg >> 1) << 3) + lr);
                uint32_t kb = (uint32_t)(s * 32 + ((lg & 1) << 4));
                ldsm_x4(bh[fn2], sbase + Bs + SMEM_SWIZZLE_128B(row * 128 + kb));
            }
#pragma unroll
            for (int fm = 0; fm < 2; fm++)
#pragma unroll
                for (int fn2 = 0; fn2 < 4; fn2++)
#pragma unroll
                    for (int nh = 0; nh < 2; nh++)
                        mma_f16(acc[fm][fn2 * 2 + nh], ah[fm],
                                bh[fn2][nh * 2], bh[fn2][nh * 2 + 1]);
        }
        __syncthreads();
    }

    int gq = lane >> 2;
    int tq = lane & 3;
#pragma unroll
    for (int fm = 0; fm < 2; fm++) {
#pragma unroll
        for (int half = 0; half < 2; half++) {
            int row = rowBase + wm * 32 + fm * 16 + half * 8 + gq;
            if (row >= M) continue;
#pragma unroll
            for (int fn = 0; fn < 8; fn++) {
                int col = colBase + wn * 64 + fn * 8 + tq * 2;
                float c0 = acc[fm][fn][half * 2 + 0];
                float c1 = acc[fm][fn][half * 2 + 1];
                if (MODE == 0) {
                    *(__half2*)(g_h + (size_t)row * 128 + col) = __floats2half2_rn(c0, c1);
                } else {
                    float b0 = __ldg(bias + col), b1 = __ldg(bias + col + 1);
                    __stcs((float2*)(outp + (size_t)row * 512 + col),
                           make_float2(c0 + b0, c1 + b1));
                }
            }
        }
    }
}

// ---------------------------------------------------------------------------
// Gather-aggregate: warp per dst, 4B packed edges, dinv factored per node,
// batch+coefficient prefetch one ahead (hides the dependent dinv[src] load).
//   agg[d] = (sum_e dinv[s]*w*h[s] + dinv_d*h[d]) * dinv_d + b_conv
// ---------------------------------------------------------------------------
__global__ __launch_bounds__(256)
void k_gather(const float* __restrict__ bc, int n) {
    int gwarp = (blockIdx.x * blockDim.x + threadIdx.x) >> 5;
    int lane = threadIdx.x & 31;
    if (gwarp >= n) return;
    int d = gwarp;
    int beg = g_off[d];
    int end = beg + g_cnt[d];

    const __half* hlane = g_h + lane * 4;

    float dinv_d = g_dinv[d];
    uint2 hr = *(const uint2*)(hlane + (size_t)d * H_DIM);
    float2 fa = __half22float2(*reinterpret_cast<__half2*>(&hr.x));
    float2 fb = __half22float2(*reinterpret_cast<__half2*>(&hr.y));
    float4 s4 = make_float4(dinv_d * fa.x, dinv_d * fa.y, dinv_d * fb.x, dinv_d * fb.y);

    // prefetch first batch: record + coefficient
    uint32_t rec = 0u;
    float cfl = 0.0f;
    if (beg + lane < end) {
        rec = g_edges[beg + lane];
        cfl = __half2float(__ushort_as_half((unsigned short)(rec & 0xFFFFu))) *
              __ldg(&g_dinv[rec >> 16]);
    }

    for (int base = beg; base < end; base += 32) {
        uint32_t recN = 0u;
        float cflN = 0.0f;
        int nb = base + 32;
        if (nb < end && nb + lane < end) {
            recN = g_edges[nb + lane];
            cflN = __half2float(__ushort_as_half((unsigned short)(recN & 0xFFFFu))) *
                   __ldg(&g_dinv[recN >> 16]);
        }

        int cnt = min(32, end - base);
#pragma unroll
        for (int b = 0; b < 32; b += 16) {
            if (b >= cnt) break;
            uint2 rv[16];
            float cf[16];
#pragma unroll
            for (int j = 0; j < 16; j++) {
                int s = __shfl_sync(0xFFFFFFFFu, (int)(rec >> 16), b + j);
                cf[j] = __shfl_sync(0xFFFFFFFFu, cfl, b + j);
                rv[j] = *(const uint2*)(hlane + (size_t)s * H_DIM);
            }
#pragma unroll
            for (int j = 0; j < 16; j++) {
                float2 pa = __half22float2(*reinterpret_cast<__half2*>(&rv[j].x));
                float2 pb = __half22float2(*reinterpret_cast<__half2*>(&rv[j].y));
                s4.x = fmaf(cf[j], pa.x, s4.x);
                s4.y = fmaf(cf[j], pa.y, s4.y);
                s4.z = fmaf(cf[j], pb.x, s4.z);
                s4.w = fmaf(cf[j], pb.y, s4.w);
            }
        }
        rec = recN;
        cfl = cflN;
    }
    float4 bb = *(const float4*)(bc + lane * 4);
    float4 acc = make_float4(fmaf(s4.x, dinv_d, bb.x), fmaf(s4.y, dinv_d, bb.y),
                             fmaf(s4.z, dinv_d, bb.z), fmaf(s4.w, dinv_d, bb.w));
    uint2 st;
    st.x = pack_f16(acc.x, acc.y);
    st.y = pack_f16(acc.z, acc.w);
    *(uint2*)(g_aggh + (size_t)d * H_DIM + lane * 4) = st;
}

// ---------------------------------------------------------------------------
extern "C" void kernel_launch(void* const* d_in, const int* in_sizes, int n_in,
                              void* d_out, int out_size) {
    const float* x  = (const float*)d_in[0];
    const int*   ei = (const int*)  d_in[1];
    const float* ew = (const float*)d_in[2];
    const float* Wc = (const float*)d_in[3];  // [512,128]
    const float* bc = (const float*)d_in[4];
    const float* Wl = (const float*)d_in[5];  // [128,512]
    const float* bl = (const float*)d_in[6];
    float* out = (float*)d_out;

    int E = in_sizes[2];
    int n = in_sizes[0] / F_INF;
    const int* src = ei;
    const int* dst = ei + E;

    const int SMEM_BYTES = 65536;
    cudaFuncSetAttribute(gemm_f16<0>, cudaFuncAttributeMaxDynamicSharedMemorySize, SMEM_BYTES);
    cudaFuncSetAttribute(gemm_f16<1>, cudaFuncAttributeMaxDynamicSharedMemorySize, SMEM_BYTES);

    __half *wc16, *wl16;
    cudaGetSymbolAddress((void**)&wc16, g_wc16);
    cudaGetSymbolAddress((void**)&wl16, g_wl16);

    // One-time side-stream + events (host resources, not device allocations).
    static cudaStream_t s2 = nullptr;
    static cudaEvent_t evFork = nullptr, evJoin = nullptr;
    if (s2 == nullptr) {
        cudaStreamCreateWithFlags(&s2, cudaStreamNonBlocking);
        cudaEventCreateWithFlags(&evFork, cudaEventDisableTiming);
        cudaEventCreateWithFlags(&evJoin, cudaEventDisableTiming);
    }

    // 1) init (deg2 reset + fp16 weight transposes) — root of both branches
    k_init<<<(H_DIM * F_INF + 255) / 256, 256>>>(Wc, Wl, n);

    // Fork: GEMM1 (needs only x, wc16) runs on s2 concurrently with edge prep.
    cudaEventRecord(evFork, 0);
    cudaStreamWaitEvent(s2, evFork, 0);
    {
        dim3 grid(1, (n + 127) / 128);
        gemm_f16<0><<<grid, 256, SMEM_BYTES, s2>>>(x, wc16, nullptr, nullptr, n, F_INF);
    }

    // Edge-prep branch on the main stream (fill: no dinv reads, 4B records)
    k_deg_accum<<<(E + 255) / 256, 256>>>(dst, ew, E);
    k_dinv_assign<<<(n + 255) / 256, 256>>>(n);
    k_fill<<<(E + 255) / 256, 256>>>(src, dst, ew, E);

    // Join: gather needs both g_h (s2) and g_edges/g_off/g_cnt/g_dinv (main)
    cudaEventRecord(evJoin, s2);
    cudaStreamWaitEvent(0, evJoin, 0);

    // gather-aggregate -> fp16 agg
    {
        int blocks = (n * 32 + 255) / 256;
        k_gather<<<blocks, 256>>>(bc, n);
    }

    // GEMM2: out = agg @ Wl + b_lin
    {
        dim3 grid(F_INF / 128, (n + 127) / 128);
        gemm_f16<1><<<grid, 256, SMEM_BYTES>>>(nullptr, wl16, bl, out, n, H_DIM);
    }
}